// round 10
// baseline (speedup 1.0000x reference)
#include <cuda_runtime.h>
#include <cuda_bf16.h>
#include <math_constants.h>
#include <cstdint>

// ---------------- problem constants ----------------
#define NN   50000
#define EE   800000
#define HD   256          // H*D
#define HH   4
#define DD   64
#define EPSL 1e-5f

// ---------------- device scratch ----------------
__device__ float g_feat[NN * HD];     // feat = BN(h) @ W
__device__ float g_h[NN * HD];        // layer activations (pre-BN)
__device__ float g_el[NN * HH];
__device__ float g_er[NN * HH];
__device__ int   g_deg[NN];
__device__ int   g_rowptr[NN + 1];
__device__ int   g_cursor[NN];
__device__ int   g_srcs[EE];
__device__ __nv_bfloat16 g_Bh[HD * HD];   // W^T hi  [n][k]
__device__ __nv_bfloat16 g_Bl[HD * HD];   // W^T lo  [n][k]
#define NBLK_SC 196
__device__ int   g_bsum[NBLK_SC];
__device__ int   g_boff[NBLK_SC];
#define NBLK_BN 296
__device__ float g_psum[NBLK_BN * HD];
__device__ float g_psq [NBLK_BN * HD];
__device__ float g_scale[HD];
__device__ float g_shift[HD];

// ---------------- helpers ----------------
__device__ __forceinline__ uint32_t smem_u32(const void* p) {
    uint32_t a;
    asm("{ .reg .u64 t; cvta.to.shared.u64 t, %1; cvt.u32.u64 %0, t; }" : "=r"(a) : "l"(p));
    return a;
}
__device__ __forceinline__ void ldsm4(uint32_t* r, uint32_t addr) {
    asm volatile("ldmatrix.sync.aligned.m8n8.x4.shared.b16 {%0,%1,%2,%3}, [%4];"
        : "=r"(r[0]), "=r"(r[1]), "=r"(r[2]), "=r"(r[3]) : "r"(addr));
}
__device__ __forceinline__ void mma16816(float* c, const uint32_t* a, const uint32_t* b) {
    asm volatile("mma.sync.aligned.m16n8k16.row.col.f32.bf16.bf16.f32 "
        "{%0,%1,%2,%3}, {%4,%5,%6,%7}, {%8,%9}, {%0,%1,%2,%3};"
        : "+f"(c[0]), "+f"(c[1]), "+f"(c[2]), "+f"(c[3])
        : "r"(a[0]), "r"(a[1]), "r"(a[2]), "r"(a[3]), "r"(b[0]), "r"(b[1]));
}
__device__ __forceinline__ uint32_t pack_bf16(float a, float b) {
    __nv_bfloat162 h = __floats2bfloat162_rn(a, b);
    return *(uint32_t*)&h;
}

// ---------------- CSR build ----------------
__global__ void k_zero_deg() {
    int i = blockIdx.x * blockDim.x + threadIdx.x;
    if (i < NN) g_deg[i] = 0;
}
__global__ void k_hist(const int* __restrict__ dst) {
    int i = blockIdx.x * blockDim.x + threadIdx.x;
    if (i < EE) atomicAdd(&g_deg[dst[i]], 1);
}
__global__ void k_bsum() {
    __shared__ int sm[256];
    int t = threadIdx.x;
    int i = blockIdx.x * 256 + t;
    sm[t] = (i < NN) ? g_deg[i] : 0;
    __syncthreads();
    #pragma unroll
    for (int off = 128; off > 0; off >>= 1) {
        if (t < off) sm[t] += sm[t + off];
        __syncthreads();
    }
    if (t == 0) g_bsum[blockIdx.x] = sm[0];
}
__global__ void k_scan_bsums() {
    __shared__ int sm[256];
    int t = threadIdx.x;
    int v = (t < NBLK_SC) ? g_bsum[t] : 0;
    sm[t] = v;
    __syncthreads();
    #pragma unroll
    for (int off = 1; off < 256; off <<= 1) {
        int tv = (t >= off) ? sm[t - off] : 0;
        __syncthreads();
        sm[t] += tv;
        __syncthreads();
    }
    if (t < NBLK_SC) g_boff[t] = sm[t] - v;
}
__global__ void k_rowptr() {
    __shared__ int sm[256];
    int t = threadIdx.x;
    int i = blockIdx.x * 256 + t;
    int v = (i < NN) ? g_deg[i] : 0;
    sm[t] = v;
    __syncthreads();
    #pragma unroll
    for (int off = 1; off < 256; off <<= 1) {
        int tv = (t >= off) ? sm[t - off] : 0;
        __syncthreads();
        sm[t] += tv;
        __syncthreads();
    }
    int excl = sm[t] - v + g_boff[blockIdx.x];
    if (i < NN) { g_rowptr[i] = excl; g_cursor[i] = excl; }
    if (i == 0) g_rowptr[NN] = EE;
}
__global__ void k_scatter(const int* __restrict__ src, const int* __restrict__ dst) {
    int i = blockIdx.x * blockDim.x + threadIdx.x;
    if (i < EE) {
        int p = atomicAdd(&g_cursor[dst[i]], 1);
        g_srcs[p] = src[i];
    }
}

// ---------------- weight prep: transpose + bf16 hi/lo split ----------------
__global__ void k_prepW(const float* __restrict__ W) {
    int idx = blockIdx.x * blockDim.x + threadIdx.x;   // k*256 + n
    if (idx >= HD * HD) return;
    int k = idx >> 8, n = idx & 255;
    float w = W[idx];
    __nv_bfloat16 h = __float2bfloat16_rn(w);
    __nv_bfloat16 l = __float2bfloat16_rn(w - __bfloat162float(h));
    g_Bh[n * HD + k] = h;
    g_Bl[n * HD + k] = l;
}

// ---------------- bf16x3 HMMA GEMM + fused BN(A) + fused el/er epilogue ----
// CTA 128x128, warps 4(M)x2(N), warp tile 32x64 (=1 head). K chunks of 32.
// Double-buffered SMEM: 2 stages x (AH 8K | AL 8K | BH 8K | BL 8K) = 64KB.
#define STG 32768u
__global__ void __launch_bounds__(256)
k_gemm_mma(const float* __restrict__ A, float* __restrict__ C,
           const float* __restrict__ alv, const float* __restrict__ arv, int useBN) {
    extern __shared__ __align__(1024) uint8_t sm[];
    const uint32_t sb = smem_u32(sm);

    int tid = threadIdx.x, wid = tid >> 5, lane = tid & 31;
    int m0 = blockIdx.y * 128, n0 = blockIdx.x * 128;
    int wm = (wid & 3) * 32, wn = (wid >> 2) * 64;

    float acc[2][8][4];
    #pragma unroll
    for (int a = 0; a < 2; a++)
        #pragma unroll
        for (int b = 0; b < 8; b++)
            #pragma unroll
            for (int c = 0; c < 4; c++) acc[a][b][c] = 0.f;

    // ---- load-phase addressing ----
    int r = tid >> 1, half = tid & 1;
    bool okA = (m0 + r) < NN;
    const float* Arow = A + (size_t)(okA ? m0 + r : 0) * HD + half * 16;
    const __nv_bfloat16* Bhp = g_Bh + (size_t)(n0 + r) * HD + half * 16;
    const __nv_bfloat16* Blp = g_Bl + (size_t)(n0 + r) * HD + half * 16;
    uint32_t xr = ((r >> 1) & 3) << 4;
    uint32_t off0 = (uint32_t)r * 64 + ((half * 32 + 0)  ^ xr);
    uint32_t off1 = (uint32_t)r * 64 + ((half * 32 + 16) ^ xr);

    // ---- mma-phase addressing ----
    int sub = lane >> 3, l7 = lane & 7;
    int arow = wm + (sub & 1) * 8 + l7;
    uint32_t aRowOff = (uint32_t)arow * 64;
    uint32_t aXor = ((arow >> 1) & 3) << 4;
    uint32_t aChk = (uint32_t)(sub >> 1) * 16;
    int brow = wn + (sub >> 1) * 8 + l7;
    uint32_t bRowOff = (uint32_t)brow * 64;
    uint32_t bXor = ((brow >> 1) & 3) << 4;
    uint32_t bChk = (uint32_t)(sub & 1) * 16;

    float4 pa[4];
    uint4 pbh[2], pbl[2];

#define LOADREGS(KC) do { \
    if (okA) { \
        const float4* p = (const float4*)(Arow + (KC) * 32); \
        pa[0] = p[0]; pa[1] = p[1]; pa[2] = p[2]; pa[3] = p[3]; \
    } else { \
        pa[0] = pa[1] = pa[2] = pa[3] = make_float4(0.f, 0.f, 0.f, 0.f); \
    } \
    const uint4* ph = (const uint4*)(Bhp + (KC) * 32); \
    const uint4* pl = (const uint4*)(Blp + (KC) * 32); \
    pbh[0] = ph[0]; pbh[1] = ph[1]; \
    pbl[0] = pl[0]; pbl[1] = pl[1]; \
} while (0)

#define STOREREGS(ST, KC) do { \
    if (useBN) { \
        int c0 = ((KC) * 32 + half * 16) >> 2; \
        const float4* s4 = (const float4*)g_scale + c0; \
        const float4* t4p = (const float4*)g_shift + c0; \
        _Pragma("unroll") \
        for (int j = 0; j < 4; j++) { \
            float4 s = s4[j], t = t4p[j]; \
            pa[j].x = fmaf(pa[j].x, s.x, t.x); \
            pa[j].y = fmaf(pa[j].y, s.y, t.y); \
            pa[j].z = fmaf(pa[j].z, s.z, t.z); \
            pa[j].w = fmaf(pa[j].w, s.w, t.w); \
        } \
    } \
    float v[16]; \
    *(float4*)&v[0] = pa[0]; *(float4*)&v[4] = pa[1]; \
    *(float4*)&v[8] = pa[2]; *(float4*)&v[12] = pa[3]; \
    uint32_t hh[8], ll[8]; \
    _Pragma("unroll") \
    for (int i = 0; i < 8; i++) { \
        __nv_bfloat16 ha = __float2bfloat16_rn(v[2 * i]); \
        __nv_bfloat16 hb = __float2bfloat16_rn(v[2 * i + 1]); \
        hh[i] = pack_bf16(v[2 * i], v[2 * i + 1]); \
        ll[i] = pack_bf16(v[2 * i]     - __bfloat162float(ha), \
                          v[2 * i + 1] - __bfloat162float(hb)); \
    } \
    uint8_t* base = sm + (ST) * STG; \
    *(uint4*)(base + off0)          = make_uint4(hh[0], hh[1], hh[2], hh[3]); \
    *(uint4*)(base + off1)          = make_uint4(hh[4], hh[5], hh[6], hh[7]); \
    *(uint4*)(base + 8192 + off0)   = make_uint4(ll[0], ll[1], ll[2], ll[3]); \
    *(uint4*)(base + 8192 + off1)   = make_uint4(ll[4], ll[5], ll[6], ll[7]); \
    *(uint4*)(base + 16384 + off0)  = pbh[0]; \
    *(uint4*)(base + 16384 + off1)  = pbh[1]; \
    *(uint4*)(base + 24576 + off0)  = pbl[0]; \
    *(uint4*)(base + 24576 + off1)  = pbl[1]; \
} while (0)

#define COMPUTE(ST) do { \
    uint32_t AHs = sb + (ST) * STG; \
    uint32_t ALs = AHs + 8192, BHs = AHs + 16384, BLs = AHs + 24576; \
    _Pragma("unroll") \
    for (int k16 = 0; k16 < 2; k16++) { \
        uint32_t kb = (uint32_t)k16 * 32; \
        uint32_t aoff = (aChk | kb) ^ aXor; \
        uint32_t boff = (bChk | kb) ^ bXor; \
        uint32_t ah[2][4], al[2][4]; \
        _Pragma("unroll") \
        for (int mi = 0; mi < 2; mi++) { \
            ldsm4(ah[mi], AHs + aRowOff + mi * 1024 + aoff); \
            ldsm4(al[mi], ALs + aRowOff + mi * 1024 + aoff); \
        } \
        uint32_t bh[4][4], bl[4][4]; \
        _Pragma("unroll") \
        for (int nf = 0; nf < 4; nf++) { \
            ldsm4(bh[nf], BHs + bRowOff + nf * 1024 + boff); \
            ldsm4(bl[nf], BLs + bRowOff + nf * 1024 + boff); \
        } \
        _Pragma("unroll") \
        for (int mi = 0; mi < 2; mi++) \
            _Pragma("unroll") \
            for (int nf = 0; nf < 4; nf++) \
                _Pragma("unroll") \
                for (int hn = 0; hn < 2; hn++) { \
                    float* c = acc[mi][nf * 2 + hn]; \
                    mma16816(c, ah[mi], &bh[nf][hn * 2]); \
                    mma16816(c, ah[mi], &bl[nf][hn * 2]); \
                    mma16816(c, al[mi], &bh[nf][hn * 2]); \
                } \
    } \
} while (0)

    // ---- software pipeline: 2 stages, 1 sync per chunk ----
    LOADREGS(0);
    STOREREGS(0, 0);
    __syncthreads();
    #pragma unroll
    for (int kc = 0; kc < 8; kc++) {
        if (kc < 7) LOADREGS(kc + 1);
        COMPUTE(kc & 1);
        if (kc < 7) {
            STOREREGS((kc + 1) & 1, kc + 1);
            __syncthreads();
        }
    }

    // ---- epilogue 1: store C ----
    int gid = lane >> 2, t4 = lane & 3;
    #pragma unroll
    for (int mi = 0; mi < 2; mi++) {
        int row = m0 + wm + mi * 16 + gid;
        #pragma unroll
        for (int nb = 0; nb < 8; nb++) {
            int col = n0 + wn + nb * 8 + t4 * 2;
            if (row < NN)
                *(float2*)(C + (size_t)row * HD + col) =
                    make_float2(acc[mi][nb][0], acc[mi][nb][1]);
            if (row + 8 < NN)
                *(float2*)(C + (size_t)(row + 8) * HD + col) =
                    make_float2(acc[mi][nb][2], acc[mi][nb][3]);
        }
    }

    // ---- epilogue 2: fused el/er (warp tile = exactly one head) ----
    {
        int head = blockIdx.x * 2 + (wid >> 2);
        const float* alh = alv + head * 64;
        const float* arh = arv + head * 64;
        float av0[8], av1[8], rv0[8], rv1[8];
        #pragma unroll
        for (int nb = 0; nb < 8; nb++) {
            int c = nb * 8 + t4 * 2;
            av0[nb] = __ldg(alh + c);
            av1[nb] = __ldg(alh + c + 1);
            rv0[nb] = __ldg(arh + c);
            rv1[nb] = __ldg(arh + c + 1);
        }
        #pragma unroll
        for (int mi = 0; mi < 2; mi++) {
            float elo = 0.f, ehi = 0.f, rlo = 0.f, rhi = 0.f;
            #pragma unroll
            for (int nb = 0; nb < 8; nb++) {
                elo = fmaf(acc[mi][nb][0], av0[nb], fmaf(acc[mi][nb][1], av1[nb], elo));
                ehi = fmaf(acc[mi][nb][2], av0[nb], fmaf(acc[mi][nb][3], av1[nb], ehi));
                rlo = fmaf(acc[mi][nb][0], rv0[nb], fmaf(acc[mi][nb][1], rv1[nb], rlo));
                rhi = fmaf(acc[mi][nb][2], rv0[nb], fmaf(acc[mi][nb][3], rv1[nb], rhi));
            }
            #pragma unroll
            for (int d = 1; d <= 2; d <<= 1) {
                elo += __shfl_xor_sync(0xffffffffu, elo, d);
                ehi += __shfl_xor_sync(0xffffffffu, ehi, d);
                rlo += __shfl_xor_sync(0xffffffffu, rlo, d);
                rhi += __shfl_xor_sync(0xffffffffu, rhi, d);
            }
            if (t4 == 0) {
                int row0 = m0 + wm + mi * 16 + gid;
                if (row0 < NN)     { g_el[row0 * 4 + head] = elo; g_er[row0 * 4 + head] = rlo; }
                if (row0 + 8 < NN) { g_el[(row0 + 8) * 4 + head] = ehi; g_er[(row0 + 8) * 4 + head] = rhi; }
            }
        }
    }
}

// ---------------- aggregation: 1 warp/node, online softmax, fused BN residual
__global__ void __launch_bounds__(128)
k_aggregate(const float* __restrict__ hin, const float* __restrict__ bias,
            float* __restrict__ out, int act, int finalMean, int bnRes) {
    int warp = threadIdx.x >> 5;
    int lane = threadIdx.x & 31;
    int v = blockIdx.x * 4 + warp;
    if (v >= NN) return;

    int rs = g_rowptr[v];
    int re = g_rowptr[v + 1];

    int   myh = lane >> 3;
    float er2 = g_er[v * 4 + myh];

    float m = -CUDART_INF_F, denom = 0.f;
    float4 acc0 = make_float4(0.f, 0.f, 0.f, 0.f);
    float4 acc1 = make_float4(0.f, 0.f, 0.f, 0.f);
    const float4* feat4 = (const float4*)g_feat;
    int fo = lane * 2;
    for (int i = rs; i < re; i++) {
        int s = g_srcs[i];
        float t = g_el[s * 4 + myh] + er2;
        t = t > 0.f ? t : 0.2f * t;
        float mnew = fmaxf(m, t);
        float corr = __expf(m - mnew);
        float ee = __expf(t - mnew);
        m = mnew;
        denom = fmaf(denom, corr, ee);
        float4 f0 = feat4[(size_t)s * 64 + fo];
        float4 f1 = feat4[(size_t)s * 64 + fo + 1];
        acc0.x = fmaf(acc0.x, corr, ee * f0.x);
        acc0.y = fmaf(acc0.y, corr, ee * f0.y);
        acc0.z = fmaf(acc0.z, corr, ee * f0.z);
        acc0.w = fmaf(acc0.w, corr, ee * f0.w);
        acc1.x = fmaf(acc1.x, corr, ee * f1.x);
        acc1.y = fmaf(acc1.y, corr, ee * f1.y);
        acc1.z = fmaf(acc1.z, corr, ee * f1.z);
        acc1.w = fmaf(acc1.w, corr, ee * f1.w);
    }

    float inv = 1.f / fmaxf(denom, 1e-9f);
    float r[8];
    r[0] = acc0.x * inv; r[1] = acc0.y * inv; r[2] = acc0.z * inv; r[3] = acc0.w * inv;
    r[4] = acc1.x * inv; r[5] = acc1.y * inv; r[6] = acc1.z * inv; r[7] = acc1.w * inv;

    // residual (BN applied inline if bnRes) + bias
    const float4* hin4 = (const float4*)(hin + (size_t)v * HD);
    const float4* b4   = (const float4*)bias;
    float4 hv0 = hin4[fo], hv1 = hin4[fo + 1];
    if (bnRes) {
        const float4* sc4 = (const float4*)g_scale;
        const float4* sh4 = (const float4*)g_shift;
        float4 s0 = sc4[fo], s1 = sc4[fo + 1], t0 = sh4[fo], t1 = sh4[fo + 1];
        hv0.x = fmaf(hv0.x, s0.x, t0.x); hv0.y = fmaf(hv0.y, s0.y, t0.y);
        hv0.z = fmaf(hv0.z, s0.z, t0.z); hv0.w = fmaf(hv0.w, s0.w, t0.w);
        hv1.x = fmaf(hv1.x, s1.x, t1.x); hv1.y = fmaf(hv1.y, s1.y, t1.y);
        hv1.z = fmaf(hv1.z, s1.z, t1.z); hv1.w = fmaf(hv1.w, s1.w, t1.w);
    }
    float4 bv0 = b4[fo], bv1 = b4[fo + 1];
    r[0] += hv0.x + bv0.x; r[1] += hv0.y + bv0.y; r[2] += hv0.z + bv0.z; r[3] += hv0.w + bv0.w;
    r[4] += hv1.x + bv1.x; r[5] += hv1.y + bv1.y; r[6] += hv1.z + bv1.z; r[7] += hv1.w + bv1.w;

    if (act) {
        #pragma unroll
        for (int j = 0; j < 8; j++) r[j] = r[j] > 0.f ? r[j] : 0.01f * r[j];
    }

    if (!finalMean) {
        float* op = out + (size_t)v * HD + lane * 8;
        *(float4*)op       = make_float4(r[0], r[1], r[2], r[3]);
        *(float4*)(op + 4) = make_float4(r[4], r[5], r[6], r[7]);
    } else {
        #pragma unroll
        for (int j = 0; j < 8; j++) {
            r[j] += __shfl_xor_sync(0xffffffffu, r[j], 8);
            r[j] += __shfl_xor_sync(0xffffffffu, r[j], 16);
            r[j] *= 0.25f;
        }
        if (lane < 8) {
            float* op = out + (size_t)v * DD + lane * 8;
            *(float4*)op       = make_float4(r[0], r[1], r[2], r[3]);
            *(float4*)(op + 4) = make_float4(r[4], r[5], r[6], r[7]);
        }
    }
}

// ---------------- BatchNorm statistics (apply is fused into consumers) -----
__global__ void __launch_bounds__(256) k_bn_partial(const float* __restrict__ h) {
    int c   = threadIdx.x;
    int blk = blockIdx.x;
    const int rows_per = (NN + NBLK_BN - 1) / NBLK_BN;   // 169
    int r0 = blk * rows_per;
    int r1 = min(r0 + rows_per, NN);
    float s = 0.f, ss = 0.f;
    for (int r = r0; r < r1; r++) {
        float v = h[(size_t)r * HD + c];
        s += v; ss += v * v;
    }
    g_psum[blk * HD + c] = s;
    g_psq [blk * HD + c] = ss;
}
__global__ void k_bn_final(const float* __restrict__ gamma, const float* __restrict__ beta) {
    int c = threadIdx.x;
    float s = 0.f, ss = 0.f;
    for (int b = 0; b < NBLK_BN; b++) { s += g_psum[b * HD + c]; ss += g_psq[b * HD + c]; }
    float mu  = s / (float)NN;
    float var = ss / (float)NN - mu * mu;
    float sc  = gamma[c] * rsqrtf(var + EPSL);
    g_scale[c] = sc;
    g_shift[c] = beta[c] - mu * sc;
}

// ---------------- launch ----------------
extern "C" void kernel_launch(void* const* d_in, const int* in_sizes, int n_in,
                              void* d_out, int out_size) {
    const float* x   = (const float*)d_in[0];
    const int*   src = (const int*)d_in[1];
    const int*   dst = (const int*)d_in[2];
    const float* W1  = (const float*)d_in[3];
    const float* al1 = (const float*)d_in[4];
    const float* ar1 = (const float*)d_in[5];
    const float* b1  = (const float*)d_in[6];
    const float* W2  = (const float*)d_in[7];
    const float* al2 = (const float*)d_in[8];
    const float* ar2 = (const float*)d_in[9];
    const float* b2  = (const float*)d_in[10];
    const float* W3  = (const float*)d_in[11];
    const float* al3 = (const float*)d_in[12];
    const float* ar3 = (const float*)d_in[13];
    const float* b3  = (const float*)d_in[14];
    const float* g1  = (const float*)d_in[15];
    const float* be1 = (const float*)d_in[16];
    const float* g2  = (const float*)d_in[17];
    const float* be2 = (const float*)d_in[18];
    float* out = (float*)d_out;
    (void)in_sizes; (void)n_in; (void)out_size;

    float *d_feat, *d_h;
    cudaGetSymbolAddress((void**)&d_feat, g_feat);
    cudaGetSymbolAddress((void**)&d_h,    g_h);

    cudaFuncSetAttribute(k_gemm_mma, cudaFuncAttributeMaxDynamicSharedMemorySize, 65536);

    dim3 gemmGrid(2, (NN + 127) / 128);   // (2, 391)
    int aggGrid = NN / 4;

    // launch order puts gemm at index 3 (0-based) so ncu profiles it
    k_zero_deg<<<(NN + 255) / 256, 256>>>();                          // 0
    k_hist<<<(EE + 255) / 256, 256>>>(dst);                           // 1
    k_prepW<<<HD * HD / 256, 256>>>(W1);                              // 2
    k_gemm_mma<<<gemmGrid, 256, 65536>>>(x, d_feat, al1, ar1, 0);     // 3  <- profiled
    k_bsum<<<NBLK_SC, 256>>>();                                       // 4
    k_scan_bsums<<<1, 256>>>();                                       // 5
    k_rowptr<<<NBLK_SC, 256>>>();                                     // 6
    k_scatter<<<(EE + 255) / 256, 256>>>(src, dst);                   // 7

    // ---- layer 1 (rest) ----
    k_aggregate<<<aggGrid, 128>>>(x, b1, d_h, 1, 0, 0);
    k_bn_partial<<<NBLK_BN, 256>>>(d_h);
    k_bn_final<<<1, 256>>>(g1, be1);

    // ---- layer 2 ----
    k_prepW<<<HD * HD / 256, 256>>>(W2);
    k_gemm_mma<<<gemmGrid, 256, 65536>>>(d_h, d_feat, al2, ar2, 1);
    k_aggregate<<<aggGrid, 128>>>(d_h, b2, d_h, 1, 0, 1);
    k_bn_partial<<<NBLK_BN, 256>>>(d_h);
    k_bn_final<<<1, 256>>>(g2, be2);

    // ---- layer 3 ----
    k_prepW<<<HD * HD / 256, 256>>>(W3);
    k_gemm_mma<<<gemmGrid, 256, 65536>>>(d_h, d_feat, al3, ar3, 1);
    k_aggregate<<<aggGrid, 128>>>(d_h, b3, out, 0, 1, 1);
}

// round 11
// speedup vs baseline: 1.0060x; 1.0060x over previous
#include <cuda_runtime.h>
#include <cuda_bf16.h>
#include <math_constants.h>
#include <cstdint>

// ---------------- problem constants ----------------
#define NN   50000
#define EE   800000
#define HD   256          // H*D
#define HH   4
#define DD   64
#define EPSL 1e-5f

// ---------------- device scratch ----------------
__device__ float g_feat[NN * HD];     // feat = BN(h) @ W
__device__ float g_h[NN * HD];        // layer activations (pre-BN)
__device__ float g_el[NN * HH];
__device__ float g_er[NN * HH];
__device__ int   g_deg[NN];
__device__ int   g_rowptr[NN + 1];
__device__ int   g_cursor[NN];
__device__ int   g_srcs[EE];
__device__ __nv_bfloat16 g_Bh[HD * HD];   // W^T hi  [n][k]
__device__ __nv_bfloat16 g_Bl[HD * HD];   // W^T lo  [n][k]
#define NBLK_SC 196
__device__ int   g_bsum[NBLK_SC];
__device__ int   g_boff[NBLK_SC];
#define NBLK_BN 296
__device__ float g_psum[NBLK_BN * HD];
__device__ float g_psq [NBLK_BN * HD];
__device__ float g_scale[HD];
__device__ float g_shift[HD];

// ---------------- helpers ----------------
__device__ __forceinline__ uint32_t smem_u32(const void* p) {
    uint32_t a;
    asm("{ .reg .u64 t; cvta.to.shared.u64 t, %1; cvt.u32.u64 %0, t; }" : "=r"(a) : "l"(p));
    return a;
}
__device__ __forceinline__ void ldsm4(uint32_t* r, uint32_t addr) {
    asm volatile("ldmatrix.sync.aligned.m8n8.x4.shared.b16 {%0,%1,%2,%3}, [%4];"
        : "=r"(r[0]), "=r"(r[1]), "=r"(r[2]), "=r"(r[3]) : "r"(addr));
}
__device__ __forceinline__ void mma16816(float* c, const uint32_t* a, const uint32_t* b) {
    asm volatile("mma.sync.aligned.m16n8k16.row.col.f32.bf16.bf16.f32 "
        "{%0,%1,%2,%3}, {%4,%5,%6,%7}, {%8,%9}, {%0,%1,%2,%3};"
        : "+f"(c[0]), "+f"(c[1]), "+f"(c[2]), "+f"(c[3])
        : "r"(a[0]), "r"(a[1]), "r"(a[2]), "r"(a[3]), "r"(b[0]), "r"(b[1]));
}
__device__ __forceinline__ uint32_t pack_bf16(float a, float b) {
    __nv_bfloat162 h = __floats2bfloat162_rn(a, b);
    return *(uint32_t*)&h;
}

// ---------------- CSR build ----------------
__global__ void k_zero_deg() {
    int i = blockIdx.x * blockDim.x + threadIdx.x;
    if (i < NN) g_deg[i] = 0;
}
__global__ void k_hist(const int* __restrict__ dst) {
    int i = blockIdx.x * blockDim.x + threadIdx.x;
    if (i < EE) atomicAdd(&g_deg[dst[i]], 1);
}
__global__ void k_bsum() {
    __shared__ int sm[256];
    int t = threadIdx.x;
    int i = blockIdx.x * 256 + t;
    sm[t] = (i < NN) ? g_deg[i] : 0;
    __syncthreads();
    #pragma unroll
    for (int off = 128; off > 0; off >>= 1) {
        if (t < off) sm[t] += sm[t + off];
        __syncthreads();
    }
    if (t == 0) g_bsum[blockIdx.x] = sm[0];
}
__global__ void k_scan_bsums() {
    __shared__ int sm[256];
    int t = threadIdx.x;
    int v = (t < NBLK_SC) ? g_bsum[t] : 0;
    sm[t] = v;
    __syncthreads();
    #pragma unroll
    for (int off = 1; off < 256; off <<= 1) {
        int tv = (t >= off) ? sm[t - off] : 0;
        __syncthreads();
        sm[t] += tv;
        __syncthreads();
    }
    if (t < NBLK_SC) g_boff[t] = sm[t] - v;
}
__global__ void k_rowptr() {
    __shared__ int sm[256];
    int t = threadIdx.x;
    int i = blockIdx.x * 256 + t;
    int v = (i < NN) ? g_deg[i] : 0;
    sm[t] = v;
    __syncthreads();
    #pragma unroll
    for (int off = 1; off < 256; off <<= 1) {
        int tv = (t >= off) ? sm[t - off] : 0;
        __syncthreads();
        sm[t] += tv;
        __syncthreads();
    }
    int excl = sm[t] - v + g_boff[blockIdx.x];
    if (i < NN) { g_rowptr[i] = excl; g_cursor[i] = excl; }
    if (i == 0) g_rowptr[NN] = EE;
}
__global__ void k_scatter(const int* __restrict__ src, const int* __restrict__ dst) {
    int i = blockIdx.x * blockDim.x + threadIdx.x;
    if (i < EE) {
        int p = atomicAdd(&g_cursor[dst[i]], 1);
        g_srcs[p] = src[i];
    }
}

// ---------------- weight prep: transpose + bf16 hi/lo split ----------------
__global__ void k_prepW(const float* __restrict__ W) {
    int idx = blockIdx.x * blockDim.x + threadIdx.x;   // k*256 + n
    if (idx >= HD * HD) return;
    int k = idx >> 8, n = idx & 255;
    float w = W[idx];
    __nv_bfloat16 h = __float2bfloat16_rn(w);
    __nv_bfloat16 l = __float2bfloat16_rn(w - __bfloat162float(h));
    g_Bh[n * HD + k] = h;
    g_Bl[n * HD + k] = l;
}

// ---------------- bf16x3 HMMA GEMM + fused BN(A) + fused el/er epilogue ----
// CTA 128x128, warps 4(M)x2(N), warp tile 32x64 (=1 head). K chunks of 32.
// Double-buffered SMEM: 2 stages x (AH 8K | AL 8K | BH 8K | BL 8K) = 64KB.
#define STG 32768u
__global__ void __launch_bounds__(256)
k_gemm_mma(const float* __restrict__ A, float* __restrict__ C,
           const float* __restrict__ alv, const float* __restrict__ arv, int useBN) {
    extern __shared__ __align__(1024) uint8_t sm[];
    const uint32_t sb = smem_u32(sm);

    int tid = threadIdx.x, wid = tid >> 5, lane = tid & 31;
    int m0 = blockIdx.y * 128, n0 = blockIdx.x * 128;
    int wm = (wid & 3) * 32, wn = (wid >> 2) * 64;

    float acc[2][8][4];
    #pragma unroll
    for (int a = 0; a < 2; a++)
        #pragma unroll
        for (int b = 0; b < 8; b++)
            #pragma unroll
            for (int c = 0; c < 4; c++) acc[a][b][c] = 0.f;

    // ---- load-phase addressing ----
    int r = tid >> 1, half = tid & 1;
    bool okA = (m0 + r) < NN;
    const float* Arow = A + (size_t)(okA ? m0 + r : 0) * HD + half * 16;
    const __nv_bfloat16* Bhp = g_Bh + (size_t)(n0 + r) * HD + half * 16;
    const __nv_bfloat16* Blp = g_Bl + (size_t)(n0 + r) * HD + half * 16;
    uint32_t xr = ((r >> 1) & 3) << 4;
    uint32_t off0 = (uint32_t)r * 64 + ((half * 32 + 0)  ^ xr);
    uint32_t off1 = (uint32_t)r * 64 + ((half * 32 + 16) ^ xr);

    // ---- mma-phase addressing ----
    int sub = lane >> 3, l7 = lane & 7;
    int arow = wm + (sub & 1) * 8 + l7;
    uint32_t aRowOff = (uint32_t)arow * 64;
    uint32_t aXor = ((arow >> 1) & 3) << 4;
    uint32_t aChk = (uint32_t)(sub >> 1) * 16;
    int brow = wn + (sub >> 1) * 8 + l7;
    uint32_t bRowOff = (uint32_t)brow * 64;
    uint32_t bXor = ((brow >> 1) & 3) << 4;
    uint32_t bChk = (uint32_t)(sub & 1) * 16;

    float4 pa[4];
    uint4 pbh[2], pbl[2];

#define LOADREGS(KC) do { \
    if (okA) { \
        const float4* p = (const float4*)(Arow + (KC) * 32); \
        pa[0] = p[0]; pa[1] = p[1]; pa[2] = p[2]; pa[3] = p[3]; \
    } else { \
        pa[0] = pa[1] = pa[2] = pa[3] = make_float4(0.f, 0.f, 0.f, 0.f); \
    } \
    const uint4* ph = (const uint4*)(Bhp + (KC) * 32); \
    const uint4* pl = (const uint4*)(Blp + (KC) * 32); \
    pbh[0] = ph[0]; pbh[1] = ph[1]; \
    pbl[0] = pl[0]; pbl[1] = pl[1]; \
} while (0)

#define STOREREGS(ST, KC) do { \
    if (useBN) { \
        int c0 = ((KC) * 32 + half * 16) >> 2; \
        const float4* s4 = (const float4*)g_scale + c0; \
        const float4* t4p = (const float4*)g_shift + c0; \
        _Pragma("unroll") \
        for (int j = 0; j < 4; j++) { \
            float4 s = s4[j], t = t4p[j]; \
            pa[j].x = fmaf(pa[j].x, s.x, t.x); \
            pa[j].y = fmaf(pa[j].y, s.y, t.y); \
            pa[j].z = fmaf(pa[j].z, s.z, t.z); \
            pa[j].w = fmaf(pa[j].w, s.w, t.w); \
        } \
    } \
    float v[16]; \
    *(float4*)&v[0] = pa[0]; *(float4*)&v[4] = pa[1]; \
    *(float4*)&v[8] = pa[2]; *(float4*)&v[12] = pa[3]; \
    uint32_t hh[8], ll[8]; \
    _Pragma("unroll") \
    for (int i = 0; i < 8; i++) { \
        __nv_bfloat16 ha = __float2bfloat16_rn(v[2 * i]); \
        __nv_bfloat16 hb = __float2bfloat16_rn(v[2 * i + 1]); \
        hh[i] = pack_bf16(v[2 * i], v[2 * i + 1]); \
        ll[i] = pack_bf16(v[2 * i]     - __bfloat162float(ha), \
                          v[2 * i + 1] - __bfloat162float(hb)); \
    } \
    uint8_t* base = sm + (ST) * STG; \
    *(uint4*)(base + off0)          = make_uint4(hh[0], hh[1], hh[2], hh[3]); \
    *(uint4*)(base + off1)          = make_uint4(hh[4], hh[5], hh[6], hh[7]); \
    *(uint4*)(base + 8192 + off0)   = make_uint4(ll[0], ll[1], ll[2], ll[3]); \
    *(uint4*)(base + 8192 + off1)   = make_uint4(ll[4], ll[5], ll[6], ll[7]); \
    *(uint4*)(base + 16384 + off0)  = pbh[0]; \
    *(uint4*)(base + 16384 + off1)  = pbh[1]; \
    *(uint4*)(base + 24576 + off0)  = pbl[0]; \
    *(uint4*)(base + 24576 + off1)  = pbl[1]; \
} while (0)

#define COMPUTE(ST) do { \
    uint32_t AHs = sb + (ST) * STG; \
    uint32_t ALs = AHs + 8192, BHs = AHs + 16384, BLs = AHs + 24576; \
    _Pragma("unroll") \
    for (int k16 = 0; k16 < 2; k16++) { \
        uint32_t kb = (uint32_t)k16 * 32; \
        uint32_t aoff = (aChk | kb) ^ aXor; \
        uint32_t boff = (bChk | kb) ^ bXor; \
        uint32_t ah[2][4], al[2][4]; \
        _Pragma("unroll") \
        for (int mi = 0; mi < 2; mi++) { \
            ldsm4(ah[mi], AHs + aRowOff + mi * 1024 + aoff); \
            ldsm4(al[mi], ALs + aRowOff + mi * 1024 + aoff); \
        } \
        uint32_t bh[4][4], bl[4][4]; \
        _Pragma("unroll") \
        for (int nf = 0; nf < 4; nf++) { \
            ldsm4(bh[nf], BHs + bRowOff + nf * 1024 + boff); \
            ldsm4(bl[nf], BLs + bRowOff + nf * 1024 + boff); \
        } \
        _Pragma("unroll") \
        for (int mi = 0; mi < 2; mi++) \
            _Pragma("unroll") \
            for (int nf = 0; nf < 4; nf++) \
                _Pragma("unroll") \
                for (int hn = 0; hn < 2; hn++) { \
                    float* c = acc[mi][nf * 2 + hn]; \
                    mma16816(c, ah[mi], &bh[nf][hn * 2]); \
                    mma16816(c, ah[mi], &bl[nf][hn * 2]); \
                    mma16816(c, al[mi], &bh[nf][hn * 2]); \
                } \
    } \
} while (0)

    // ---- software pipeline: 2 stages, 1 sync per chunk ----
    LOADREGS(0);
    STOREREGS(0, 0);
    __syncthreads();
    #pragma unroll
    for (int kc = 0; kc < 8; kc++) {
        if (kc < 7) LOADREGS(kc + 1);
        COMPUTE(kc & 1);
        if (kc < 7) {
            STOREREGS((kc + 1) & 1, kc + 1);
            __syncthreads();
        }
    }

    // ---- epilogue 1: store C ----
    int gid = lane >> 2, t4 = lane & 3;
    #pragma unroll
    for (int mi = 0; mi < 2; mi++) {
        int row = m0 + wm + mi * 16 + gid;
        #pragma unroll
        for (int nb = 0; nb < 8; nb++) {
            int col = n0 + wn + nb * 8 + t4 * 2;
            if (row < NN)
                *(float2*)(C + (size_t)row * HD + col) =
                    make_float2(acc[mi][nb][0], acc[mi][nb][1]);
            if (row + 8 < NN)
                *(float2*)(C + (size_t)(row + 8) * HD + col) =
                    make_float2(acc[mi][nb][2], acc[mi][nb][3]);
        }
    }

    // ---- epilogue 2: fused el/er (warp tile = exactly one head) ----
    {
        int head = blockIdx.x * 2 + (wid >> 2);
        const float* alh = alv + head * 64;
        const float* arh = arv + head * 64;
        float av0[8], av1[8], rv0[8], rv1[8];
        #pragma unroll
        for (int nb = 0; nb < 8; nb++) {
            int c = nb * 8 + t4 * 2;
            av0[nb] = __ldg(alh + c);
            av1[nb] = __ldg(alh + c + 1);
            rv0[nb] = __ldg(arh + c);
            rv1[nb] = __ldg(arh + c + 1);
        }
        #pragma unroll
        for (int mi = 0; mi < 2; mi++) {
            float elo = 0.f, ehi = 0.f, rlo = 0.f, rhi = 0.f;
            #pragma unroll
            for (int nb = 0; nb < 8; nb++) {
                elo = fmaf(acc[mi][nb][0], av0[nb], fmaf(acc[mi][nb][1], av1[nb], elo));
                ehi = fmaf(acc[mi][nb][2], av0[nb], fmaf(acc[mi][nb][3], av1[nb], ehi));
                rlo = fmaf(acc[mi][nb][0], rv0[nb], fmaf(acc[mi][nb][1], rv1[nb], rlo));
                rhi = fmaf(acc[mi][nb][2], rv0[nb], fmaf(acc[mi][nb][3], rv1[nb], rhi));
            }
            #pragma unroll
            for (int d = 1; d <= 2; d <<= 1) {
                elo += __shfl_xor_sync(0xffffffffu, elo, d);
                ehi += __shfl_xor_sync(0xffffffffu, ehi, d);
                rlo += __shfl_xor_sync(0xffffffffu, rlo, d);
                rhi += __shfl_xor_sync(0xffffffffu, rhi, d);
            }
            if (t4 == 0) {
                int row0 = m0 + wm + mi * 16 + gid;
                if (row0 < NN)     { g_el[row0 * 4 + head] = elo; g_er[row0 * 4 + head] = rlo; }
                if (row0 + 8 < NN) { g_el[(row0 + 8) * 4 + head] = ehi; g_er[(row0 + 8) * 4 + head] = rhi; }
            }
        }
    }
}

// ---------------- aggregation: 1 warp/node, online softmax, fused BN residual
__global__ void __launch_bounds__(128)
k_aggregate(const float* __restrict__ hin, const float* __restrict__ bias,
            float* __restrict__ out, int act, int finalMean, int bnRes) {
    int warp = threadIdx.x >> 5;
    int lane = threadIdx.x & 31;
    int v = blockIdx.x * 4 + warp;
    if (v >= NN) return;

    int rs = g_rowptr[v];
    int re = g_rowptr[v + 1];

    int   myh = lane >> 3;
    float er2 = g_er[v * 4 + myh];

    float m = -CUDART_INF_F, denom = 0.f;
    float4 acc0 = make_float4(0.f, 0.f, 0.f, 0.f);
    float4 acc1 = make_float4(0.f, 0.f, 0.f, 0.f);
    const float4* feat4 = (const float4*)g_feat;
    int fo = lane * 2;
    for (int i = rs; i < re; i++) {
        int s = g_srcs[i];
        float t = g_el[s * 4 + myh] + er2;
        t = t > 0.f ? t : 0.2f * t;
        float mnew = fmaxf(m, t);
        float corr = __expf(m - mnew);
        float ee = __expf(t - mnew);
        m = mnew;
        denom = fmaf(denom, corr, ee);
        float4 f0 = feat4[(size_t)s * 64 + fo];
        float4 f1 = feat4[(size_t)s * 64 + fo + 1];
        acc0.x = fmaf(acc0.x, corr, ee * f0.x);
        acc0.y = fmaf(acc0.y, corr, ee * f0.y);
        acc0.z = fmaf(acc0.z, corr, ee * f0.z);
        acc0.w = fmaf(acc0.w, corr, ee * f0.w);
        acc1.x = fmaf(acc1.x, corr, ee * f1.x);
        acc1.y = fmaf(acc1.y, corr, ee * f1.y);
        acc1.z = fmaf(acc1.z, corr, ee * f1.z);
        acc1.w = fmaf(acc1.w, corr, ee * f1.w);
    }

    float inv = 1.f / fmaxf(denom, 1e-9f);
    float r[8];
    r[0] = acc0.x * inv; r[1] = acc0.y * inv; r[2] = acc0.z * inv; r[3] = acc0.w * inv;
    r[4] = acc1.x * inv; r[5] = acc1.y * inv; r[6] = acc1.z * inv; r[7] = acc1.w * inv;

    // residual (BN applied inline if bnRes) + bias
    const float4* hin4 = (const float4*)(hin + (size_t)v * HD);
    const float4* b4   = (const float4*)bias;
    float4 hv0 = hin4[fo], hv1 = hin4[fo + 1];
    if (bnRes) {
        const float4* sc4 = (const float4*)g_scale;
        const float4* sh4 = (const float4*)g_shift;
        float4 s0 = sc4[fo], s1 = sc4[fo + 1], t0 = sh4[fo], t1 = sh4[fo + 1];
        hv0.x = fmaf(hv0.x, s0.x, t0.x); hv0.y = fmaf(hv0.y, s0.y, t0.y);
        hv0.z = fmaf(hv0.z, s0.z, t0.z); hv0.w = fmaf(hv0.w, s0.w, t0.w);
        hv1.x = fmaf(hv1.x, s1.x, t1.x); hv1.y = fmaf(hv1.y, s1.y, t1.y);
        hv1.z = fmaf(hv1.z, s1.z, t1.z); hv1.w = fmaf(hv1.w, s1.w, t1.w);
    }
    float4 bv0 = b4[fo], bv1 = b4[fo + 1];
    r[0] += hv0.x + bv0.x; r[1] += hv0.y + bv0.y; r[2] += hv0.z + bv0.z; r[3] += hv0.w + bv0.w;
    r[4] += hv1.x + bv1.x; r[5] += hv1.y + bv1.y; r[6] += hv1.z + bv1.z; r[7] += hv1.w + bv1.w;

    if (act) {
        #pragma unroll
        for (int j = 0; j < 8; j++) r[j] = r[j] > 0.f ? r[j] : 0.01f * r[j];
    }

    if (!finalMean) {
        float* op = out + (size_t)v * HD + lane * 8;
        *(float4*)op       = make_float4(r[0], r[1], r[2], r[3]);
        *(float4*)(op + 4) = make_float4(r[4], r[5], r[6], r[7]);
    } else {
        #pragma unroll
        for (int j = 0; j < 8; j++) {
            r[j] += __shfl_xor_sync(0xffffffffu, r[j], 8);
            r[j] += __shfl_xor_sync(0xffffffffu, r[j], 16);
            r[j] *= 0.25f;
        }
        if (lane < 8) {
            float* op = out + (size_t)v * DD + lane * 8;
            *(float4*)op       = make_float4(r[0], r[1], r[2], r[3]);
            *(float4*)(op + 4) = make_float4(r[4], r[5], r[6], r[7]);
        }
    }
}

// ---------------- BatchNorm statistics (apply is fused into consumers) -----
__global__ void __launch_bounds__(256) k_bn_partial(const float* __restrict__ h) {
    int c   = threadIdx.x;
    int blk = blockIdx.x;
    const int rows_per = (NN + NBLK_BN - 1) / NBLK_BN;   // 169
    int r0 = blk * rows_per;
    int r1 = min(r0 + rows_per, NN);
    float s = 0.f, ss = 0.f;
    for (int r = r0; r < r1; r++) {
        float v = h[(size_t)r * HD + c];
        s += v; ss += v * v;
    }
    g_psum[blk * HD + c] = s;
    g_psq [blk * HD + c] = ss;
}
__global__ void k_bn_final(const float* __restrict__ gamma, const float* __restrict__ beta) {
    int c = threadIdx.x;
    float s = 0.f, ss = 0.f;
    for (int b = 0; b < NBLK_BN; b++) { s += g_psum[b * HD + c]; ss += g_psq[b * HD + c]; }
    float mu  = s / (float)NN;
    float var = ss / (float)NN - mu * mu;
    float sc  = gamma[c] * rsqrtf(var + EPSL);
    g_scale[c] = sc;
    g_shift[c] = beta[c] - mu * sc;
}

// ---------------- launch ----------------
extern "C" void kernel_launch(void* const* d_in, const int* in_sizes, int n_in,
                              void* d_out, int out_size) {
    const float* x   = (const float*)d_in[0];
    const int*   src = (const int*)d_in[1];
    const int*   dst = (const int*)d_in[2];
    const float* W1  = (const float*)d_in[3];
    const float* al1 = (const float*)d_in[4];
    const float* ar1 = (const float*)d_in[5];
    const float* b1  = (const float*)d_in[6];
    const float* W2  = (const float*)d_in[7];
    const float* al2 = (const float*)d_in[8];
    const float* ar2 = (const float*)d_in[9];
    const float* b2  = (const float*)d_in[10];
    const float* W3  = (const float*)d_in[11];
    const float* al3 = (const float*)d_in[12];
    const float* ar3 = (const float*)d_in[13];
    const float* b3  = (const float*)d_in[14];
    const float* g1  = (const float*)d_in[15];
    const float* be1 = (const float*)d_in[16];
    const float* g2  = (const float*)d_in[17];
    const float* be2 = (const float*)d_in[18];
    float* out = (float*)d_out;
    (void)in_sizes; (void)n_in; (void)out_size;

    float *d_feat, *d_h;
    cudaGetSymbolAddress((void**)&d_feat, g_feat);
    cudaGetSymbolAddress((void**)&d_h,    g_h);

    cudaFuncSetAttribute(k_gemm_mma, cudaFuncAttributeMaxDynamicSharedMemorySize, 65536);

    dim3 gemmGrid(2, (NN + 127) / 128);   // (2, 391)
    int aggGrid = NN / 4;

    // launch order puts gemm at index 3 (0-based) so ncu profiles it
    k_zero_deg<<<(NN + 255) / 256, 256>>>();                          // 0
    k_hist<<<(EE + 255) / 256, 256>>>(dst);                           // 1
    k_prepW<<<HD * HD / 256, 256>>>(W1);                              // 2
    k_gemm_mma<<<gemmGrid, 256, 65536>>>(x, d_feat, al1, ar1, 0);     // 3  <- profiled
    k_bsum<<<NBLK_SC, 256>>>();                                       // 4
    k_scan_bsums<<<1, 256>>>();                                       // 5
    k_rowptr<<<NBLK_SC, 256>>>();                                     // 6
    k_scatter<<<(EE + 255) / 256, 256>>>(src, dst);                   // 7

    // ---- layer 1 (rest) ----
    k_aggregate<<<aggGrid, 128>>>(x, b1, d_h, 1, 0, 0);
    k_bn_partial<<<NBLK_BN, 256>>>(d_h);
    k_bn_final<<<1, 256>>>(g1, be1);

    // ---- layer 2 ----
    k_prepW<<<HD * HD / 256, 256>>>(W2);
    k_gemm_mma<<<gemmGrid, 256, 65536>>>(d_h, d_feat, al2, ar2, 1);
    k_aggregate<<<aggGrid, 128>>>(d_h, b2, d_h, 1, 0, 1);
    k_bn_partial<<<NBLK_BN, 256>>>(d_h);
    k_bn_final<<<1, 256>>>(g2, be2);

    // ---- layer 3 ----
    k_prepW<<<HD * HD / 256, 256>>>(W3);
    k_gemm_mma<<<gemmGrid, 256, 65536>>>(d_h, d_feat, al3, ar3, 1);
    k_aggregate<<<aggGrid, 128>>>(d_h, b3, out, 0, 1, 1);
}